// round 2
// baseline (speedup 1.0000x reference)
#include <cuda_runtime.h>
#include <cstdint>

#define N_A   30000
#define N_NBH 48
#define NF    128
#define NS    25

typedef unsigned long long ull;

__device__ __forceinline__ ull pk2(float a, float b) {
    ull r; asm("mov.b64 %0,{%1,%2};" : "=l"(r) : "f"(a), "f"(b)); return r;
}
__device__ __forceinline__ void upk2(ull v, float& a, float& b) {
    asm("mov.b64 {%0,%1},%2;" : "=f"(a), "=f"(b) : "l"(v));
}
__device__ __forceinline__ ull ffma2(ull a, ull b, ull c) {
    ull d; asm("fma.rn.f32x2 %0,%1,%2,%3;" : "=l"(d) : "l"(a), "l"(b), "l"(c)); return d;
}
// shifted softplus: log(1+e^x) - log(2), stable form
__device__ __forceinline__ float sspf(float x) {
    float e = __expf(-fabsf(x));
    return fmaxf(x, 0.f) + __logf(1.f + e) - 0.6931471805599453f;
}

// scratch (static device arrays — no runtime allocation)
__device__ __align__(16) float g_y  [(size_t)N_A * NF];
__device__ __align__(16) float g_agg[(size_t)N_A * NF];
__device__ __align__(16) float g_t  [(size_t)N_A * NF];

// ---------------------------------------------------------------------------
// Generic (M x 128) @ (128 x 128) GEMM, optional bias and ssp activation.
// BM=64 rows per block, 256 threads, whole B + A-tile in smem, f32x2 FMAs.
// ---------------------------------------------------------------------------
template<bool BIAS, bool ACT>
__global__ void __launch_bounds__(256, 2)
gemm128(const float* __restrict__ A, const float* __restrict__ B,
        const float* __restrict__ bias, float* __restrict__ C, int M)
{
    extern __shared__ float sm[];
    float* sA = sm;            // 64*128
    float* sB = sm + 64 * NF;  // 128*128
    const int tid  = threadIdx.x;
    const int row0 = blockIdx.x * 64;

    for (int i = tid; i < (NF * NF) / 4; i += 256)
        ((float4*)sB)[i] = ((const float4*)B)[i];
    for (int i = tid; i < (64 * NF) / 4; i += 256) {
        int r = row0 + (i >> 5);   // 32 float4 per row
        float4 v = make_float4(0.f, 0.f, 0.f, 0.f);
        if (r < M) v = ((const float4*)A)[(size_t)row0 * 32 + i];
        ((float4*)sA)[i] = v;
    }
    __syncthreads();

    const int tx = tid & 31, ty = tid >> 5;
    const int c0 = tx * 4;
    ull a0[8], a1[8];
    const ull z = pk2(0.f, 0.f);
#pragma unroll
    for (int i = 0; i < 8; i++) { a0[i] = z; a1[i] = z; }

#pragma unroll 4
    for (int k = 0; k < NF; k++) {
        float4 b4 = *(const float4*)(sB + k * NF + c0);
        ull b01 = pk2(b4.x, b4.y), b23 = pk2(b4.z, b4.w);
#pragma unroll
        for (int i = 0; i < 8; i++) {
            float h = sA[(ty * 8 + i) * NF + k];
            ull hh = pk2(h, h);
            a0[i] = ffma2(hh, b01, a0[i]);
            a1[i] = ffma2(hh, b23, a1[i]);
        }
    }

    float bb0 = 0.f, bb1 = 0.f, bb2 = 0.f, bb3 = 0.f;
    if (BIAS) { bb0 = bias[c0]; bb1 = bias[c0 + 1]; bb2 = bias[c0 + 2]; bb3 = bias[c0 + 3]; }
#pragma unroll
    for (int i = 0; i < 8; i++) {
        int r = row0 + ty * 8 + i;
        if (r < M) {
            float o0, o1, o2, o3;
            upk2(a0[i], o0, o1); upk2(a1[i], o2, o3);
            o0 += bb0; o1 += bb1; o2 += bb2; o3 += bb3;
            if (ACT) { o0 = sspf(o0); o1 = sspf(o1); o2 = sspf(o2); o3 = sspf(o3); }
            *(float4*)(C + (size_t)r * NF + c0) = make_float4(o0, o1, o2, o3);
        }
    }
}

// ---------------------------------------------------------------------------
// Fused CFConv core. Persistent blocks; per atom:
//   H = ssp(dRe @ Wf1 + bf1)              (48 x 128, smem)
//   W = H @ Wf2 + bf2                     (48 x 128, registers, f32x2)
//   agg[a] = sum_n mask * y[nbr[n]] * W[n]
// smem (floats): W2 16384 | W1 3200 | H 6144 | overlay(dRe2 2400 / red 1024)
//                | nbr 48 | mask 48   => 28224 floats = 112896 B
// ---------------------------------------------------------------------------
__global__ void __launch_bounds__(256, 2)
fused_cfconv(const float* __restrict__ dre_g, const int* __restrict__ nbr_g,
             const float* __restrict__ mask_g, const float* __restrict__ Wf1,
             const float* __restrict__ bf1, const float* __restrict__ Wf2,
             const float* __restrict__ bf2)
{
    extern __shared__ float sm[];
    float* s_W2   = sm;              // 16384
    float* s_W1   = sm + 16384;      // 3200
    float* s_H    = sm + 19584;      // 6144
    float* s_ovl  = sm + 25728;      // 2400 (dRe splatted) / 1024 (reduction)
    int*   s_nbr  = (int*)(sm + 28128);
    float* s_mask = sm + 28176;

    const int tid = threadIdx.x;

    // weights once per block
    for (int i = tid; i < 16384 / 4; i += 256) ((float4*)s_W2)[i] = ((const float4*)Wf2)[i];
    for (int i = tid; i < 3200 / 4;  i += 256) ((float4*)s_W1)[i] = ((const float4*)Wf1)[i];

    // stage-1 thread mapping: column pair 2*f2, row group rg (12 rows each)
    const int f2 = tid & 63, rg = tid >> 6;
    const ull b1p = pk2(bf1[2 * f2], bf1[2 * f2 + 1]);
    // stage-2 thread mapping: 6 rows x 4 cols per thread
    const int tx = tid & 31, ty = tid >> 5;
    const int c0 = tx * 4;
    const ull b2a = pk2(bf2[c0], bf2[c0 + 1]);
    const ull b2b = pk2(bf2[c0 + 2], bf2[c0 + 3]);
    const int rbase = ty * 6;
    const float* yb = g_y + c0;

    __syncthreads();

    for (int a = blockIdx.x; a < N_A; a += gridDim.x) {
        // load per-atom data; dRe is stored splatted (v,v) for f32x2 stage-1
        const float* dre = dre_g + (size_t)a * (N_NBH * NS);
        for (int i = tid; i < N_NBH * NS; i += 256) {
            float v = __ldg(dre + i);
            s_ovl[2 * i] = v; s_ovl[2 * i + 1] = v;
        }
        if (tid < N_NBH) {
            s_nbr[tid]  = nbr_g[(size_t)a * N_NBH + tid];
            s_mask[tid] = mask_g[(size_t)a * N_NBH + tid];
        }
        __syncthreads();

        // ---- stage 1: H = ssp(dRe @ Wf1 + bf1) ----
        const float* w1c = s_W1 + 2 * f2;
#pragma unroll
        for (int i = 0; i < 12; i++) {
            int r = rg * 12 + i;
            ull acc = b1p;
            const ull* dr = (const ull*)s_ovl + r * NS;   // splatted pairs
#pragma unroll
            for (int s = 0; s < NS; s++) {
                ull wp = *(const ull*)(w1c + s * NF);
                acc = ffma2(dr[s], wp, acc);
            }
            float h0, h1; upk2(acc, h0, h1);
            h0 = sspf(h0); h1 = sspf(h1);
            *(float2*)(s_H + r * NF + 2 * f2) = make_float2(h0, h1);
        }
        __syncthreads();

        // ---- stage 2: W = H @ Wf2 + bf2 (register tile 6x4, f32x2) ----
        ull aw0[6], aw1[6];
#pragma unroll
        for (int i = 0; i < 6; i++) { aw0[i] = b2a; aw1[i] = b2b; }
        const float* hb = s_H + rbase * NF;
#pragma unroll 4
        for (int k = 0; k < NF; k++) {
            float4 b4 = *(const float4*)(s_W2 + k * NF + c0);
            ull b01 = pk2(b4.x, b4.y), b23 = pk2(b4.z, b4.w);
#pragma unroll
            for (int i = 0; i < 6; i++) {
                float h = hb[i * NF + k];
                ull hh = pk2(h, h);
                aw0[i] = ffma2(hh, b01, aw0[i]);
                aw1[i] = ffma2(hh, b23, aw1[i]);
            }
        }

        // ---- epilogue: gather y (L2-resident), mask, partial reduce ----
        float p0 = 0.f, p1 = 0.f, p2 = 0.f, p3 = 0.f;
#pragma unroll
        for (int i = 0; i < 6; i++) {
            int   r = rbase + i;
            int   j = s_nbr[r];
            float m = s_mask[r];
            float4 yv = __ldg((const float4*)(yb + (size_t)j * NF));
            float w0, w1, w2, w3;
            upk2(aw0[i], w0, w1); upk2(aw1[i], w2, w3);
            p0 += m * yv.x * w0; p1 += m * yv.y * w1;
            p2 += m * yv.z * w2; p3 += m * yv.w * w3;
        }
        // dRe2 region dead after stage 1 -> reuse as red[8][128]
        *(float4*)(s_ovl + ty * NF + c0) = make_float4(p0, p1, p2, p3);
        __syncthreads();
        if (tid < NF) {
            float ssum = 0.f;
#pragma unroll
            for (int t2 = 0; t2 < 8; t2++) ssum += s_ovl[t2 * NF + tid];
            g_agg[(size_t)a * NF + tid] = ssum;
        }
        __syncthreads();   // protect red/dRe2 overlay before next iteration
    }
}

// ---------------------------------------------------------------------------
// Launch
// ---------------------------------------------------------------------------
extern "C" void kernel_launch(void* const* d_in, const int* in_sizes, int n_in,
                              void* d_out, int out_size)
{
    const float* x     = (const float*)d_in[0];
    // d_in[1] = dR (unused by reference)
    const int*   nbr   = (const int*)  d_in[2];
    const float* pmask = (const float*)d_in[3];
    const float* dre   = (const float*)d_in[4];
    const float* Wf1   = (const float*)d_in[5];
    const float* bf1   = (const float*)d_in[6];
    const float* Wf2   = (const float*)d_in[7];
    const float* bf2   = (const float*)d_in[8];
    const float* Win2f = (const float*)d_in[9];
    const float* Wf2o  = (const float*)d_in[10];
    const float* bf2o  = (const float*)d_in[11];
    const float* Wd    = (const float*)d_in[12];
    const float* bd    = (const float*)d_in[13];
    float* out = (float*)d_out;

    float *py, *pagg, *pt;
    cudaGetSymbolAddress((void**)&py,   g_y);
    cudaGetSymbolAddress((void**)&pagg, g_agg);
    cudaGetSymbolAddress((void**)&pt,   g_t);

    const int GEMM_SM  = (64 + 128) * 128 * 4;   // 98304
    const int FUSED_SM = 28224 * 4;              // 112896

    cudaFuncSetAttribute(gemm128<false, false>, cudaFuncAttributeMaxDynamicSharedMemorySize, GEMM_SM);
    cudaFuncSetAttribute(gemm128<true,  true >, cudaFuncAttributeMaxDynamicSharedMemorySize, GEMM_SM);
    cudaFuncSetAttribute(gemm128<true,  false>, cudaFuncAttributeMaxDynamicSharedMemorySize, GEMM_SM);
    cudaFuncSetAttribute(fused_cfconv, cudaFuncAttributeMaxDynamicSharedMemorySize, FUSED_SM);

    const int gblocks = (N_A + 63) / 64;

    // y = x @ W_in2f
    gemm128<false, false><<<gblocks, 256, GEMM_SM>>>(x, Win2f, nullptr, py, N_A);
    // agg = sum_n mask * y[nbr] * (ssp(dRe@Wf1+bf1) @ Wf2 + bf2)
    fused_cfconv<<<296, 256, FUSED_SM>>>(dre, nbr, pmask, Wf1, bf1, Wf2, bf2);
    // t = ssp(agg @ W_f2out + b_f2out)
    gemm128<true, true><<<gblocks, 256, GEMM_SM>>>(pagg, Wf2o, bf2o, pt, N_A);
    // out = t @ W_dense + b_dense
    gemm128<true, false><<<gblocks, 256, GEMM_SM>>>(pt, Wd, bd, out, N_A);
}

// round 3
// speedup vs baseline: 1.3582x; 1.3582x over previous
#include <cuda_runtime.h>
#include <cstdint>

#define N_A   30000
#define N_NBH 48
#define NF    128
#define NS    25

typedef unsigned long long ull;

__device__ __forceinline__ ull pk2(float a, float b) {
    ull r; asm("mov.b64 %0,{%1,%2};" : "=l"(r) : "f"(a), "f"(b)); return r;
}
__device__ __forceinline__ void upk2(ull v, float& a, float& b) {
    asm("mov.b64 {%0,%1},%2;" : "=f"(a), "=f"(b) : "l"(v));
}
__device__ __forceinline__ ull ffma2(ull a, ull b, ull c) {
    ull d; asm("fma.rn.f32x2 %0,%1,%2,%3;" : "=l"(d) : "l"(a), "l"(b), "l"(c)); return d;
}
// shifted softplus: log(1+e^x) - log(2), stable form
__device__ __forceinline__ float sspf(float x) {
    float e = __expf(-fabsf(x));
    return fmaxf(x, 0.f) + __logf(1.f + e) - 0.6931471805599453f;
}
// fp32 -> tf32 (round to nearest) kept in b32 reg
__device__ __forceinline__ uint32_t tf32b(float f) {
    uint32_t r; asm("cvt.rna.tf32.f32 %0,%1;" : "=r"(r) : "f"(f)); return r;
}
__device__ __forceinline__ void mma_tf32(float& c0, float& c1, float& c2, float& c3,
                                         uint32_t a0, uint32_t a1, uint32_t a2, uint32_t a3,
                                         uint32_t b0, uint32_t b1) {
    asm volatile("mma.sync.aligned.m16n8k8.row.col.f32.tf32.tf32.f32 "
                 "{%0,%1,%2,%3},{%4,%5,%6,%7},{%8,%9},{%0,%1,%2,%3};"
                 : "+f"(c0), "+f"(c1), "+f"(c2), "+f"(c3)
                 : "r"(a0), "r"(a1), "r"(a2), "r"(a3), "r"(b0), "r"(b1));
}

// scratch (static device arrays — no runtime allocation)
__device__ __align__(16) float g_y  [(size_t)N_A * NF];
__device__ __align__(16) float g_agg[(size_t)N_A * NF];
__device__ __align__(16) float g_t  [(size_t)N_A * NF];

// ---------------------------------------------------------------------------
// Generic (M x 128) @ (128 x 128) fp32 GEMM, optional bias and ssp activation.
// ---------------------------------------------------------------------------
template<bool BIAS, bool ACT>
__global__ void __launch_bounds__(256, 2)
gemm128(const float* __restrict__ A, const float* __restrict__ B,
        const float* __restrict__ bias, float* __restrict__ C, int M)
{
    extern __shared__ float sm[];
    float* sA = sm;            // 64*128
    float* sB = sm + 64 * NF;  // 128*128
    const int tid  = threadIdx.x;
    const int row0 = blockIdx.x * 64;

    for (int i = tid; i < (NF * NF) / 4; i += 256)
        ((float4*)sB)[i] = ((const float4*)B)[i];
    for (int i = tid; i < (64 * NF) / 4; i += 256) {
        int r = row0 + (i >> 5);
        float4 v = make_float4(0.f, 0.f, 0.f, 0.f);
        if (r < M) v = ((const float4*)A)[(size_t)row0 * 32 + i];
        ((float4*)sA)[i] = v;
    }
    __syncthreads();

    const int tx = tid & 31, ty = tid >> 5;
    const int c0 = tx * 4;
    ull a0[8], a1[8];
    const ull z = pk2(0.f, 0.f);
#pragma unroll
    for (int i = 0; i < 8; i++) { a0[i] = z; a1[i] = z; }

#pragma unroll 4
    for (int k = 0; k < NF; k++) {
        float4 b4 = *(const float4*)(sB + k * NF + c0);
        ull b01 = pk2(b4.x, b4.y), b23 = pk2(b4.z, b4.w);
#pragma unroll
        for (int i = 0; i < 8; i++) {
            float h = sA[(ty * 8 + i) * NF + k];
            ull hh = pk2(h, h);
            a0[i] = ffma2(hh, b01, a0[i]);
            a1[i] = ffma2(hh, b23, a1[i]);
        }
    }

    float bb0 = 0.f, bb1 = 0.f, bb2 = 0.f, bb3 = 0.f;
    if (BIAS) { bb0 = bias[c0]; bb1 = bias[c0 + 1]; bb2 = bias[c0 + 2]; bb3 = bias[c0 + 3]; }
#pragma unroll
    for (int i = 0; i < 8; i++) {
        int r = row0 + ty * 8 + i;
        if (r < M) {
            float o0, o1, o2, o3;
            upk2(a0[i], o0, o1); upk2(a1[i], o2, o3);
            o0 += bb0; o1 += bb1; o2 += bb2; o3 += bb3;
            if (ACT) { o0 = sspf(o0); o1 = sspf(o1); o2 = sspf(o2); o3 = sspf(o3); }
            *(float4*)(C + (size_t)r * NF + c0) = make_float4(o0, o1, o2, o3);
        }
    }
}

// ---------------------------------------------------------------------------
// Fused CFConv core, TF32 tensor-core version.
// 512 threads = 16 warps, persistent over atoms, grid = 148.
// Stage 1 (per atom):  H = ssp(dRe @ Wf1 + bf1)      48x128, K=25 pad 32
//   warp w -> n-tile w (cols 8w..8w+8), m-tiles 0..2, B1 in registers.
// Stage 2:  W = H @ Wf2  (bias folded into epilogue)  48x128, K=128
//   warp (kq=w&1, nq=w>>1): K-halves, 2 n-tiles (16 cols), B2 in registers.
// Epilogue: per-element m*y[nbr]*W, row-reduce (shfl), kq-partials via smem,
//   bf2 handled as bf2[g]*sum(m*y[nbr,g]).
// ---------------------------------------------------------------------------
__global__ void __launch_bounds__(512, 1)
fused_cfconv(const float* __restrict__ dre_g, const int* __restrict__ nbr_g,
             const float* __restrict__ mask_g, const float* __restrict__ Wf1,
             const float* __restrict__ bf1, const float* __restrict__ Wf2,
             const float* __restrict__ bf2)
{
    __shared__ float s_dre[48 * 36];   // tf32 bits, stride 36 (pad, cols 25..31 zero)
    __shared__ float s_H  [48 * 132];  // tf32 bits, stride 132
    __shared__ float s_part[128];
    __shared__ int   s_nbr[48];
    __shared__ float s_mask[48];

    const int tid  = threadIdx.x;
    const int wid  = tid >> 5, lane = tid & 31;
    const int l4   = lane >> 2, lm = lane & 3;
    const int kq   = wid & 1,  nq = wid >> 1;

    // ---- B fragments in registers (once per block) ----
    uint32_t b1[4][2];
#pragma unroll
    for (int kt = 0; kt < 4; kt++)
#pragma unroll
        for (int j = 0; j < 2; j++) {
            int r = kt * 8 + lm + 4 * j;
            b1[kt][j] = (r < NS) ? tf32b(Wf1[r * NF + 8 * wid + l4]) : 0u;
        }
    const float bias1a = bf1[8 * wid + 2 * lm];
    const float bias1b = bf1[8 * wid + 2 * lm + 1];

    uint32_t b2[8][2][2];
#pragma unroll
    for (int kt = 0; kt < 8; kt++)
#pragma unroll
        for (int n = 0; n < 2; n++)
#pragma unroll
            for (int j = 0; j < 2; j++) {
                int r = (kq * 8 + kt) * 8 + lm + 4 * j;
                int c = 8 * (2 * nq + n) + l4;
                b2[kt][n][j] = tf32b(Wf2[r * NF + c]);
            }
    float bias2[2][2];
#pragma unroll
    for (int n = 0; n < 2; n++) {
        bias2[n][0] = bf2[16 * nq + 8 * n + 2 * lm];
        bias2[n][1] = bf2[16 * nq + 8 * n + 2 * lm + 1];
    }

    // zero the padded dRe area once (cols >= 25 stay zero forever)
    for (int i = tid; i < 48 * 36; i += 512) s_dre[i] = 0.f;
    __syncthreads();

    for (int a = blockIdx.x; a < N_A; a += gridDim.x) {
        // ---- load per-atom data ----
        const float* dre = dre_g + (size_t)a * (N_NBH * NS);
        for (int i = tid; i < N_NBH * NS; i += 512) {
            int r = i / NS, c = i - r * NS;
            s_dre[r * 36 + c] = __uint_as_float(tf32b(__ldg(dre + i)));
        }
        if (tid < N_NBH) {
            s_nbr[tid]  = nbr_g[(size_t)a * N_NBH + tid];
            s_mask[tid] = mask_g[(size_t)a * N_NBH + tid];
        }
        __syncthreads();

        // ---- stage 1: H = ssp(dRe @ Wf1 + bf1), warp = n-tile wid ----
#pragma unroll
        for (int m = 0; m < 3; m++) {
            float c0 = 0.f, c1 = 0.f, c2 = 0.f, c3 = 0.f;
            const int rA = (16 * m + l4) * 36, rB = (16 * m + 8 + l4) * 36;
#pragma unroll
            for (int kt = 0; kt < 4; kt++) {
                int cc = kt * 8 + lm;
                uint32_t a0 = __float_as_uint(s_dre[rA + cc]);
                uint32_t a1 = __float_as_uint(s_dre[rB + cc]);
                uint32_t a2 = __float_as_uint(s_dre[rA + cc + 4]);
                uint32_t a3 = __float_as_uint(s_dre[rB + cc + 4]);
                mma_tf32(c0, c1, c2, c3, a0, a1, a2, a3, b1[kt][0], b1[kt][1]);
            }
            float h0 = sspf(c0 + bias1a), h1 = sspf(c1 + bias1b);
            float h2 = sspf(c2 + bias1a), h3 = sspf(c3 + bias1b);
            int colp = 8 * wid + 2 * lm;
            *(float2*)(s_H + (16 * m + l4) * 132 + colp) =
                make_float2(__uint_as_float(tf32b(h0)), __uint_as_float(tf32b(h1)));
            *(float2*)(s_H + (16 * m + 8 + l4) * 132 + colp) =
                make_float2(__uint_as_float(tf32b(h2)), __uint_as_float(tf32b(h3)));
        }
        __syncthreads();

        // ---- stage 2: W-partial = H @ Wf2 over K-half kq ----
        float acc[3][2][4];
#pragma unroll
        for (int m = 0; m < 3; m++)
#pragma unroll
            for (int n = 0; n < 2; n++)
#pragma unroll
                for (int j = 0; j < 4; j++) acc[m][n][j] = 0.f;

#pragma unroll
        for (int m = 0; m < 3; m++) {
            const int rA = (16 * m + l4) * 132, rB = (16 * m + 8 + l4) * 132;
#pragma unroll
            for (int kt = 0; kt < 8; kt++) {
                int cc = kq * 64 + kt * 8 + lm;
                uint32_t a0 = __float_as_uint(s_H[rA + cc]);
                uint32_t a1 = __float_as_uint(s_H[rB + cc]);
                uint32_t a2 = __float_as_uint(s_H[rA + cc + 4]);
                uint32_t a3 = __float_as_uint(s_H[rB + cc + 4]);
                mma_tf32(acc[m][0][0], acc[m][0][1], acc[m][0][2], acc[m][0][3],
                         a0, a1, a2, a3, b2[kt][0][0], b2[kt][0][1]);
                mma_tf32(acc[m][1][0], acc[m][1][1], acc[m][1][2], acc[m][1][3],
                         a0, a1, a2, a3, b2[kt][1][0], b2[kt][1][1]);
            }
        }

        // ---- epilogue: p[c] = sum_r m_r * y[j_r,c] * W[r,c]; sy for bias ----
        float p[2][2]  = {{0.f, 0.f}, {0.f, 0.f}};
        float sy[2][2] = {{0.f, 0.f}, {0.f, 0.f}};
#pragma unroll
        for (int m = 0; m < 3; m++) {
            int rA = 16 * m + l4, rB = rA + 8;
            int   jA = s_nbr[rA],  jB = s_nbr[rB];
            float mA = s_mask[rA], mB = s_mask[rB];
            const float* yA = g_y + (size_t)jA * NF;
            const float* yB = g_y + (size_t)jB * NF;
#pragma unroll
            for (int n = 0; n < 2; n++) {
                int c = 16 * nq + 8 * n + 2 * lm;
                float2 vA = *(const float2*)(yA + c);
                float2 vB = *(const float2*)(yB + c);
                p[n][0] += mA * vA.x * acc[m][n][0] + mB * vB.x * acc[m][n][2];
                p[n][1] += mA * vA.y * acc[m][n][1] + mB * vB.y * acc[m][n][3];
                if (kq == 0) {
                    sy[n][0] += mA * vA.x + mB * vB.x;
                    sy[n][1] += mA * vA.y + mB * vB.y;
                }
            }
        }
        // reduce over lanes sharing lm (stride-4 groups)
#pragma unroll
        for (int d = 4; d < 32; d <<= 1) {
#pragma unroll
            for (int n = 0; n < 2; n++) {
                p[n][0]  += __shfl_xor_sync(0xffffffffu, p[n][0],  d);
                p[n][1]  += __shfl_xor_sync(0xffffffffu, p[n][1],  d);
                sy[n][0] += __shfl_xor_sync(0xffffffffu, sy[n][0], d);
                sy[n][1] += __shfl_xor_sync(0xffffffffu, sy[n][1], d);
            }
        }
        if (kq == 1 && lane < 4) {
#pragma unroll
            for (int n = 0; n < 2; n++)
                *(float2*)(s_part + nq * 16 + 8 * n + 2 * lane) = make_float2(p[n][0], p[n][1]);
        }
        __syncthreads();
        if (kq == 0 && lane < 4) {
#pragma unroll
            for (int n = 0; n < 2; n++) {
                float2 q = *(const float2*)(s_part + nq * 16 + 8 * n + 2 * lane);
                float o0 = p[n][0] + q.x + bias2[n][0] * sy[n][0];
                float o1 = p[n][1] + q.y + bias2[n][1] * sy[n][1];
                *(float2*)(g_agg + (size_t)a * NF + 16 * nq + 8 * n + 2 * lane) =
                    make_float2(o0, o1);
            }
        }
        __syncthreads();   // protect s_part / s_dre / s_H before next atom
    }
}

// ---------------------------------------------------------------------------
// Launch
// ---------------------------------------------------------------------------
extern "C" void kernel_launch(void* const* d_in, const int* in_sizes, int n_in,
                              void* d_out, int out_size)
{
    const float* x     = (const float*)d_in[0];
    const int*   nbr   = (const int*)  d_in[2];
    const float* pmask = (const float*)d_in[3];
    const float* dre   = (const float*)d_in[4];
    const float* Wf1   = (const float*)d_in[5];
    const float* bf1   = (const float*)d_in[6];
    const float* Wf2   = (const float*)d_in[7];
    const float* bf2   = (const float*)d_in[8];
    const float* Win2f = (const float*)d_in[9];
    const float* Wf2o  = (const float*)d_in[10];
    const float* bf2o  = (const float*)d_in[11];
    const float* Wd    = (const float*)d_in[12];
    const float* bd    = (const float*)d_in[13];
    float* out = (float*)d_out;

    float *py, *pagg, *pt;
    cudaGetSymbolAddress((void**)&py,   g_y);
    cudaGetSymbolAddress((void**)&pagg, g_agg);
    cudaGetSymbolAddress((void**)&pt,   g_t);

    const int GEMM_SM = (64 + 128) * 128 * 4;   // 98304

    cudaFuncSetAttribute(gemm128<false, false>, cudaFuncAttributeMaxDynamicSharedMemorySize, GEMM_SM);
    cudaFuncSetAttribute(gemm128<true,  true >, cudaFuncAttributeMaxDynamicSharedMemorySize, GEMM_SM);
    cudaFuncSetAttribute(gemm128<true,  false>, cudaFuncAttributeMaxDynamicSharedMemorySize, GEMM_SM);

    const int gblocks = (N_A + 63) / 64;

    // y = x @ W_in2f
    gemm128<false, false><<<gblocks, 256, GEMM_SM>>>(x, Win2f, nullptr, py, N_A);
    // agg = sum_n mask * y[nbr] * (ssp(dRe@Wf1+bf1) @ Wf2 + bf2)   [TF32 tensor]
    fused_cfconv<<<148, 512>>>(dre, nbr, pmask, Wf1, bf1, Wf2, bf2);
    // t = ssp(agg @ W_f2out + b_f2out)
    gemm128<true, true><<<gblocks, 256, GEMM_SM>>>(pagg, Wf2o, bf2o, pt, N_A);
    // out = t @ W_dense + b_dense
    gemm128<true, false><<<gblocks, 256, GEMM_SM>>>(pt, Wd, bd, out, N_A);
}